// round 12
// baseline (speedup 1.0000x reference)
#include <cuda_runtime.h>
#include <cuda_fp16.h>
#include <cstdint>
#include <cstddef>

#define NN 8192
#define EMBD 256
#define NHID 64
#define ALPHA 0.2f

#define MROWS 128
#define KC 64
#define NB 72
#define JSPLIT 4
#define JQ (NN / JSPLIT)          // 2048
#define NCHUNK (JQ / KC)          // 32

// prefetch config: first PF_CHUNKS chunks of each (row-block, j-quarter)
#define PF_BLOCKS 128
#define PF_CHUNKS 12              // 12*64 cols = 768 ints = 192 uint4 per row

// k_attn smem: u/v tables (per j-quarter) then 2 pipeline stages
#define U_OFF 0
#define V_OFF 4096
#define STAGE0 8192
#define ADJ_SZ 32768                       // 128 rows x 256B
#define B_SZ 9216                          // 72 rows x 128B
#define STAGE_SZ (ADJ_SZ + B_SZ)           // 41984
#define NSTAGE 2
#define SMEM3_TOTAL (STAGE0 + NSTAGE * STAGE_SZ)   // 92160

#define SMEM1_TOTAL (EMBD * NHID * 4)      // 64KB W staging

// ---------------- device scratch ----------------
__device__ __half g_Bm[NB * NN];            // [c][j]: h cols (c<64), ones (64), pad 0
__device__ __half g_u[NN], g_v[NN];         // exp(t_j), exp(a*t_j)
__device__ float g_af[NN], g_bf[NN], g_iv[NN];  // exp(s), exp(a*s), exp(-s)
__device__ float g_part[JSPLIT * NN * NB];  // numer 0..63, denom 64
__device__ unsigned long long g_sink;       // prefetch DCE sink (never read)

// ---------------- helpers ----------------
__device__ __forceinline__ uint32_t smem_u32(const void* p) {
    uint32_t a;
    asm("{ .reg .u64 t; cvta.to.shared.u64 t, %1; cvt.u32.u64 %0, t; }" : "=r"(a) : "l"(p));
    return a;
}
__device__ __forceinline__ void cp_async16(uint32_t dst, const void* src) {
    asm volatile("cp.async.cg.shared.global [%0], [%1], 16;" :: "r"(dst), "l"(src));
}
__device__ __forceinline__ void ldsm4(uint32_t& r0, uint32_t& r1, uint32_t& r2, uint32_t& r3, uint32_t a) {
    asm volatile("ldmatrix.sync.aligned.m8n8.x4.shared.b16 {%0,%1,%2,%3}, [%4];"
                 : "=r"(r0), "=r"(r1), "=r"(r2), "=r"(r3) : "r"(a));
}
__device__ __forceinline__ void ldsm2(uint32_t& r0, uint32_t& r1, uint32_t a) {
    asm volatile("ldmatrix.sync.aligned.m8n8.x2.shared.b16 {%0,%1}, [%2];"
                 : "=r"(r0), "=r"(r1) : "r"(a));
}
__device__ __forceinline__ void mma16816(float* d, const uint32_t* a, uint32_t b0, uint32_t b1) {
    asm volatile("mma.sync.aligned.m16n8k16.row.col.f32.f16.f16.f32 "
                 "{%0,%1,%2,%3}, {%4,%5,%6,%7}, {%8,%9}, {%0,%1,%2,%3};"
                 : "+f"(d[0]), "+f"(d[1]), "+f"(d[2]), "+f"(d[3])
                 : "r"(a[0]), "r"(a[1]), "r"(a[2]), "r"(a[3]), "r"(b0), "r"(b1));
}
// P pair for 2 j's: adj * (u>=inva ? a*u : b*v), packed f16x2
__device__ __forceinline__ uint32_t frag(int2 w, __half2 u2, __half2 v2,
                                         __half2 a2, __half2 b2, __half2 iv2) {
    __half2 sel = __hge2(u2, iv2);
    __half2 au = __hmul2(a2, u2);
    __half2 bv = __hmul2(b2, v2);
    __half2 val = __hfma2(sel, __hsub2(au, bv), bv);
    uint32_t m = (uint32_t)w.x * 0x3C00u + (uint32_t)w.y * 0x3C000000u;
    __half2 res = __hmul2(val, *reinterpret_cast<__half2*>(&m));
    return *reinterpret_cast<uint32_t*>(&res);
}

// ===== Kernel 1 (fused): blocks [0,128) prefetch adj->L2; [128,384) do prep =====
__global__ void __launch_bounds__(256) k_prep(const float* __restrict__ inp,
                                              const float* __restrict__ W,
                                              const float* __restrict__ av,
                                              const int* __restrict__ adj) {
    extern __shared__ float Ws[];   // 64KB (prep role only)
    const int tid = threadIdx.x;
    const int bid = blockIdx.x;

    if (bid < PF_BLOCKS) {
        // ---- prefetch role: warm L2 with early chunks of every (bx, jq) ----
        const int bx = bid & 63;            // row-block
        const int jp = bid >> 6;            // covers jq = 2*jp, 2*jp+1
        unsigned long long s = 0;
#pragma unroll
        for (int h = 0; h < 2; h++) {
            const int jq = jp * 2 + h;
            const int* ab = adj + (size_t)(bx * MROWS) * NN + jq * JQ;
            for (int i = tid; i < MROWS * (PF_CHUNKS * 16); i += 256) {
                int row = i / (PF_CHUNKS * 16), seg = i % (PF_CHUNKS * 16);
                uint4 v = __ldcg(reinterpret_cast<const uint4*>(ab + (size_t)row * NN) + seg);
                s ^= (unsigned long long)(v.x ^ v.z) |
                     ((unsigned long long)(v.y ^ v.w) << 32);
            }
        }
#pragma unroll
        for (int o = 16; o; o >>= 1)
            s ^= __shfl_xor_sync(0xFFFFFFFFu, s, o);
        if ((tid & 31) == 0) atomicXor(&g_sink, s);
        return;
    }

    // ---- prep role (unchanged math) ----
    const int pb = bid - PF_BLOCKS;
#pragma unroll
    for (int i = tid; i < (EMBD * NHID) / 4; i += 256)
        reinterpret_cast<float4*>(Ws)[i] = __ldg(reinterpret_cast<const float4*>(W) + i);
    __syncthreads();

    const int rg = tid >> 4;                    // 16 row groups
    const int j0 = pb * 32 + rg * 2;            // 2 rows/thread, 32 rows/block
    const int c0 = (tid & 15) * 4;              // 4 cols/thread
    float acc[2][4];
#pragma unroll
    for (int rr = 0; rr < 2; rr++)
#pragma unroll
        for (int k = 0; k < 4; k++) acc[rr][k] = 0.f;

    const float* ir = inp + (size_t)j0 * EMBD;
#pragma unroll
    for (int k0 = 0; k0 < EMBD; k0 += 8) {
        float4 xs[2][2];
#pragma unroll
        for (int rr = 0; rr < 2; rr++) {
            xs[rr][0] = __ldg(reinterpret_cast<const float4*>(ir + (size_t)rr * EMBD + k0));
            xs[rr][1] = __ldg(reinterpret_cast<const float4*>(ir + (size_t)rr * EMBD + k0 + 4));
        }
#pragma unroll
        for (int kb = 0; kb < 8; kb++) {
            float4 w = *reinterpret_cast<const float4*>(Ws + (k0 + kb) * NHID + c0);
#pragma unroll
            for (int rr = 0; rr < 2; rr++) {
                float xv = (&xs[rr][kb >> 2].x)[kb & 3];
                acc[rr][0] += xv * w.x; acc[rr][1] += xv * w.y;
                acc[rr][2] += xv * w.z; acc[rr][3] += xv * w.w;
            }
        }
    }
    // s,t per row via 16-lane reductions
    float s[2], t[2];
#pragma unroll
    for (int rr = 0; rr < 2; rr++) {
        float ss = 0.f, tt = 0.f;
#pragma unroll
        for (int k = 0; k < 4; k++) {
            ss += acc[rr][k] * __ldg(av + c0 + k);
            tt += acc[rr][k] * __ldg(av + 64 + c0 + k);
        }
#pragma unroll
        for (int o = 1; o < 16; o <<= 1) {
            ss += __shfl_xor_sync(0xFFFFFFFFu, ss, o);
            tt += __shfl_xor_sync(0xFFFFFFFFu, tt, o);
        }
        s[rr] = ss; t[rr] = tt;
    }
    // B matrix: 2 adjacent j per col -> 4B stores
#pragma unroll
    for (int k = 0; k < 4; k++) {
        __half2 hp = __floats2half2_rn(acc[0][k], acc[1][k]);
        *reinterpret_cast<__half2*>(&g_Bm[(size_t)(c0 + k) * NN + j0]) = hp;
    }
    if ((tid & 15) == 0) {
        *reinterpret_cast<__half2*>(&g_u[j0]) = __floats2half2_rn(expf(t[0]), expf(t[1]));
        *reinterpret_cast<__half2*>(&g_v[j0]) = __floats2half2_rn(expf(ALPHA * t[0]), expf(ALPHA * t[1]));
        g_af[j0] = expf(s[0]);         g_af[j0 + 1] = expf(s[1]);
        g_bf[j0] = expf(ALPHA * s[0]); g_bf[j0 + 1] = expf(ALPHA * s[1]);
        g_iv[j0] = expf(-s[0]);        g_iv[j0 + 1] = expf(-s[1]);
        *reinterpret_cast<__half2*>(&g_Bm[(size_t)64 * NN + j0]) = __floats2half2_rn(1.f, 1.f);
#pragma unroll
        for (int c = 65; c < NB; c++)
            *reinterpret_cast<__half2*>(&g_Bm[(size_t)c * NN + j0]) = __floats2half2_rn(0.f, 0.f);
    }
}

// ============ Kernel 2: masked GEMM, 4 warps x 32 rows, 2 CTAs/SM ============
__device__ __forceinline__ void issue_chunk(uint32_t sb, const int* __restrict__ adj,
                                            int I0, int jb, int st, int tid) {
    const uint32_t stage = sb + STAGE0 + st * STAGE_SZ;
#pragma unroll
    for (int it = 0; it < 16; it++) {
        int u = tid + it * 128;
        int row = u >> 4, ku = u & 15;
        cp_async16(stage + (uint32_t)(row * 256 + ((ku * 16) ^ ((row & 7) << 4))),
                   adj + (size_t)(I0 + row) * NN + jb + ku * 4);
    }
    const uint32_t bst = stage + ADJ_SZ;
#pragma unroll
    for (int it = 0; it < 5; it++) {
        int v = tid + it * 128;
        if (v < 576) {
            int c = v >> 3, seg = v & 7;
            cp_async16(bst + (uint32_t)(c * 128 + ((seg * 16) ^ ((c & 7) << 4))),
                       g_Bm + (size_t)c * NN + jb + seg * 8);
        }
    }
    asm volatile("cp.async.commit_group;" ::: "memory");
}

__global__ void __launch_bounds__(128, 2) k_attn(const int* __restrict__ adj) {
    extern __shared__ char smem[];
    const uint32_t sb = smem_u32(smem);
    const int tid = threadIdx.x;
    const int wid = tid >> 5, lane = tid & 31;
    const int r = lane >> 2, cL = lane & 3;
    const int I0 = blockIdx.x * MROWS;
    const int jh = blockIdx.y;
    const int jbase0 = jh * JQ;

    issue_chunk(sb, adj, I0, jbase0, 0, tid);
    issue_chunk(sb, adj, I0, jbase0 + KC, 1, tid);

    __half* u_sh = reinterpret_cast<__half*>(smem + U_OFF);
    __half* v_sh = reinterpret_cast<__half*>(smem + V_OFF);
#pragma unroll
    for (int i = tid; i < JQ / 8; i += 128) {
        reinterpret_cast<float4*>(u_sh)[i] = reinterpret_cast<const float4*>(g_u + jbase0)[i];
        reinterpret_cast<float4*>(v_sh)[i] = reinterpret_cast<const float4*>(g_v + jbase0)[i];
    }

    const int ib = I0 + wid * 32 + r;
    __half2 a2[4], b2[4], iv2[4];
#pragma unroll
    for (int p = 0; p < 4; p++) {
        a2[p]  = __float2half2_rn(g_af[ib + p * 8]);
        b2[p]  = __float2half2_rn(g_bf[ib + p * 8]);
        iv2[p] = __float2half2_rn(g_iv[ib + p * 8]);
    }

    const uint32_t swzA = (uint32_t)(r << 4);
    const uint32_t swzB = (uint32_t)((lane & 7) << 4);
    const uint32_t kaddB = (uint32_t)(((lane >> 3) & 1) * 16);
    uint32_t rb[5];
#pragma unroll
    for (int g = 0; g < 4; g++)
        rb[g] = (uint32_t)(((2 * g + ((lane >> 4) & 1)) * 8 + (lane & 7)) * 128);
    rb[4] = (uint32_t)((64 + (lane & 7)) * 128);

    float acc[2][9][4];
#pragma unroll
    for (int rt = 0; rt < 2; rt++)
#pragma unroll
        for (int nt = 0; nt < 9; nt++)
#pragma unroll
            for (int k = 0; k < 4; k++) acc[rt][nt][k] = 0.f;

    for (int q = 0; q < NCHUNK; q++) {
        if (q < NCHUNK - 1) asm volatile("cp.async.wait_group 1;" ::: "memory");
        else                asm volatile("cp.async.wait_group 0;" ::: "memory");
        __syncthreads();

        const char* adjp = smem + STAGE0 + (q & 1) * STAGE_SZ;
        const uint32_t bstB = sb + STAGE0 + (q & 1) * STAGE_SZ + ADJ_SZ;
        const __half* uq = u_sh + q * KC;
        const __half* vq = v_sh + q * KC;
        const int rbase = wid * 32 + r;

#pragma unroll
        for (int ksi = 0; ksi < 4; ksi++) {
            const int ks = ksi * 16;
            __half2 u2lo = *reinterpret_cast<const __half2*>(uq + ks + 2 * cL);
            __half2 v2lo = *reinterpret_cast<const __half2*>(vq + ks + 2 * cL);
            __half2 u2hi = *reinterpret_cast<const __half2*>(uq + ks + 8 + 2 * cL);
            __half2 v2hi = *reinterpret_cast<const __half2*>(vq + ks + 8 + 2 * cL);
            const uint32_t ka = (uint32_t)(ks * 4 + cL * 8);
            const uint32_t inner = ((uint32_t)(ks * 2) + kaddB) ^ swzB;

            uint32_t bb[4][4], b8[2];
#pragma unroll
            for (int g = 0; g < 4; g++)
                ldsm4(bb[g][0], bb[g][1], bb[g][2], bb[g][3], bstB + rb[g] + inner);
            ldsm2(b8[0], b8[1], bstB + rb[4] + inner);

#pragma unroll
            for (int rt = 0; rt < 2; rt++) {
                const int r0 = rbase + rt * 16;
                int2 w00 = *reinterpret_cast<const int2*>(adjp + r0 * 256 + (ka ^ swzA));
                int2 w10 = *reinterpret_cast<const int2*>(adjp + (r0 + 8) * 256 + (ka ^ swzA));
                int2 w01 = *reinterpret_cast<const int2*>(adjp + r0 * 256 + ((ka + 32) ^ swzA));
                int2 w11 = *reinterpret_cast<const int2*>(adjp + (r0 + 8) * 256 + ((ka + 32) ^ swzA));

                uint32_t A[4];
                A[0] = frag(w00, u2lo, v2lo, a2[2 * rt], b2[2 * rt], iv2[2 * rt]);
                A[1] = frag(w10, u2lo, v2lo, a2[2 * rt + 1], b2[2 * rt + 1], iv2[2 * rt + 1]);
                A[2] = frag(w01, u2hi, v2hi, a2[2 * rt], b2[2 * rt], iv2[2 * rt]);
                A[3] = frag(w11, u2hi, v2hi, a2[2 * rt + 1], b2[2 * rt + 1], iv2[2 * rt + 1]);

#pragma unroll
                for (int g = 0; g < 4; g++) {
                    mma16816(acc[rt][2 * g], A, bb[g][0], bb[g][1]);
                    mma16816(acc[rt][2 * g + 1], A, bb[g][2], bb[g][3]);
                }
                mma16816(acc[rt][8], A, b8[0], b8[1]);
            }
        }
        __syncthreads();
        if (q + 2 < NCHUNK)
            issue_chunk(sb, adj, I0, jbase0 + (q + 2) * KC, q & 1, tid);
    }

#pragma unroll
    for (int rt = 0; rt < 2; rt++) {
        const int i0 = ib + rt * 16, i1 = i0 + 8;
        float* p0 = g_part + ((size_t)jh * NN + i0) * NB;
        float* p1 = g_part + ((size_t)jh * NN + i1) * NB;
#pragma unroll
        for (int nt = 0; nt < 9; nt++) {
            const int n = nt * 8 + 2 * cL;
            *reinterpret_cast<float2*>(p0 + n) = make_float2(acc[rt][nt][0], acc[rt][nt][1]);
            *reinterpret_cast<float2*>(p1 + n) = make_float2(acc[rt][nt][2], acc[rt][nt][3]);
        }
    }
}

// ============ Kernel 3: combine quarters, divide (4 elems/thread) ============
__global__ void __launch_bounds__(256) k_combine(float* __restrict__ out) {
    int e = blockIdx.x * 256 + threadIdx.x;
    int i = e >> 4, c = (e & 15) * 4;
    float den = 0.f;
    float4 num = make_float4(0.f, 0.f, 0.f, 0.f);
#pragma unroll
    for (int jh = 0; jh < JSPLIT; jh++) {
        const float* p = g_part + ((size_t)jh * NN + i) * NB;
        float4 x = *reinterpret_cast<const float4*>(p + c);
        num.x += x.x; num.y += x.y; num.z += x.z; num.w += x.w;
        den += p[64];
    }
    float rden = 1.f / den;
    *reinterpret_cast<float4*>(out + (size_t)i * NHID + c) =
        make_float4(num.x * rden, num.y * rden, num.z * rden, num.w * rden);
}

// ============ launcher ============
extern "C" void kernel_launch(void* const* d_in, const int* in_sizes, int n_in,
                              void* d_out, int out_size) {
    const float* inp = (const float*)d_in[0];
    const int* adj   = (const int*)d_in[1];
    const float* W   = (const float*)d_in[2];
    const float* av  = (const float*)d_in[3];
    float* out = (float*)d_out;
    (void)in_sizes; (void)n_in; (void)out_size;

    cudaFuncSetAttribute(k_prep, cudaFuncAttributeMaxDynamicSharedMemorySize, SMEM1_TOTAL);
    cudaFuncSetAttribute(k_attn, cudaFuncAttributeMaxDynamicSharedMemorySize, SMEM3_TOTAL);

    k_prep<<<PF_BLOCKS + NN / 32, 256, SMEM1_TOTAL>>>(inp, W, av, adj);
    dim3 g3(NN / MROWS, JSPLIT);
    k_attn<<<g3, 128, SMEM3_TOTAL>>>(adj);
    k_combine<<<(NN * NHID / 4) / 256, 256>>>(out);
}

// round 13
// speedup vs baseline: 1.4323x; 1.4323x over previous
#include <cuda_runtime.h>
#include <cuda_fp16.h>
#include <cstdint>
#include <cstddef>

#define NN 8192
#define EMBD 256
#define NHID 64
#define ALPHA 0.2f

#define MROWS 128
#define KC 64
#define NB 72
#define JSPLIT 4
#define JQ (NN / JSPLIT)          // 2048
#define NCHUNK (JQ / KC)          // 32

// k_attn smem: u/v tables then 4 B-only pipeline stages
#define U_OFF 0
#define V_OFF 4096
#define STAGE0 8192
#define B_SZ 9216                          // 72 rows x 128B
#define NSTAGE 4
#define SMEM3_TOTAL (STAGE0 + NSTAGE * B_SZ)   // 45056

#define SMEM1_TOTAL (EMBD * NHID * 4)      // 64KB W staging

// ---------------- device scratch ----------------
__device__ __half g_Bm[NB * NN];            // [c][j]: h cols (c<64), ones (64), pad 0
__device__ __half g_u[NN], g_v[NN];         // exp(t_j), exp(a*t_j)
__device__ float g_af[NN], g_bf[NN], g_iv[NN];  // exp(s), exp(a*s), exp(-s)
__device__ float g_part[JSPLIT * NN * NB];  // numer 0..63, denom 64

// ---------------- helpers ----------------
__device__ __forceinline__ uint32_t smem_u32(const void* p) {
    uint32_t a;
    asm("{ .reg .u64 t; cvta.to.shared.u64 t, %1; cvt.u32.u64 %0, t; }" : "=r"(a) : "l"(p));
    return a;
}
__device__ __forceinline__ void cp_async16(uint32_t dst, const void* src) {
    asm volatile("cp.async.cg.shared.global [%0], [%1], 16;" :: "r"(dst), "l"(src));
}
__device__ __forceinline__ void ldsm4(uint32_t& r0, uint32_t& r1, uint32_t& r2, uint32_t& r3, uint32_t a) {
    asm volatile("ldmatrix.sync.aligned.m8n8.x4.shared.b16 {%0,%1,%2,%3}, [%4];"
                 : "=r"(r0), "=r"(r1), "=r"(r2), "=r"(r3) : "r"(a));
}
__device__ __forceinline__ void ldsm2(uint32_t& r0, uint32_t& r1, uint32_t a) {
    asm volatile("ldmatrix.sync.aligned.m8n8.x2.shared.b16 {%0,%1}, [%2];"
                 : "=r"(r0), "=r"(r1) : "r"(a));
}
__device__ __forceinline__ void mma16816(float* d, const uint32_t* a, uint32_t b0, uint32_t b1) {
    asm volatile("mma.sync.aligned.m16n8k16.row.col.f32.f16.f16.f32 "
                 "{%0,%1,%2,%3}, {%4,%5,%6,%7}, {%8,%9}, {%0,%1,%2,%3};"
                 : "+f"(d[0]), "+f"(d[1]), "+f"(d[2]), "+f"(d[3])
                 : "r"(a[0]), "r"(a[1]), "r"(a[2]), "r"(a[3]), "r"(b0), "r"(b1));
}
// P pair for 2 j's: adj * (u>=inva ? a*u : b*v), packed f16x2
__device__ __forceinline__ uint32_t frag(int2 w, __half2 u2, __half2 v2,
                                         __half2 a2, __half2 b2, __half2 iv2) {
    __half2 sel = __hge2(u2, iv2);
    __half2 au = __hmul2(a2, u2);
    __half2 bv = __hmul2(b2, v2);
    __half2 val = __hfma2(sel, __hsub2(au, bv), bv);
    uint32_t m = (uint32_t)w.x * 0x3C00u + (uint32_t)w.y * 0x3C000000u;
    __half2 res = __hmul2(val, *reinterpret_cast<__half2*>(&m));
    return *reinterpret_cast<uint32_t*>(&res);
}

// ===== Kernel 1: h = input@W + prep, 4 rows x 4 cols per thread (best-known) =====
__global__ void __launch_bounds__(256) k_prep(const float* __restrict__ inp,
                                              const float* __restrict__ W,
                                              const float* __restrict__ av) {
    extern __shared__ float Ws[];   // 64KB
    const int tid = threadIdx.x;
#pragma unroll
    for (int i = tid; i < (EMBD * NHID) / 4; i += 256)
        reinterpret_cast<float4*>(Ws)[i] = __ldg(reinterpret_cast<const float4*>(W) + i);
    __syncthreads();

    const int rg = tid >> 4;                    // 16 row groups
    const int j0 = blockIdx.x * 64 + rg * 4;    // 4 rows/thread
    const int c0 = (tid & 15) * 4;              // 4 cols/thread
    float acc[4][4];
#pragma unroll
    for (int rr = 0; rr < 4; rr++)
#pragma unroll
        for (int k = 0; k < 4; k++) acc[rr][k] = 0.f;

    const float* ir = inp + (size_t)j0 * EMBD;
#pragma unroll
    for (int k0 = 0; k0 < EMBD; k0 += 8) {
        float4 xs[4][2];
#pragma unroll
        for (int rr = 0; rr < 4; rr++) {
            xs[rr][0] = __ldg(reinterpret_cast<const float4*>(ir + (size_t)rr * EMBD + k0));
            xs[rr][1] = __ldg(reinterpret_cast<const float4*>(ir + (size_t)rr * EMBD + k0 + 4));
        }
#pragma unroll
        for (int kb = 0; kb < 8; kb++) {
            float4 w = *reinterpret_cast<const float4*>(Ws + (k0 + kb) * NHID + c0);
#pragma unroll
            for (int rr = 0; rr < 4; rr++) {
                float xv = (&xs[rr][kb >> 2].x)[kb & 3];
                acc[rr][0] += xv * w.x; acc[rr][1] += xv * w.y;
                acc[rr][2] += xv * w.z; acc[rr][3] += xv * w.w;
            }
        }
    }
    float s[4], t[4];
#pragma unroll
    for (int rr = 0; rr < 4; rr++) {
        float ss = 0.f, tt = 0.f;
#pragma unroll
        for (int k = 0; k < 4; k++) {
            ss += acc[rr][k] * __ldg(av + c0 + k);
            tt += acc[rr][k] * __ldg(av + 64 + c0 + k);
        }
#pragma unroll
        for (int o = 1; o < 16; o <<= 1) {
            ss += __shfl_xor_sync(0xFFFFFFFFu, ss, o);
            tt += __shfl_xor_sync(0xFFFFFFFFu, tt, o);
        }
        s[rr] = ss; t[rr] = tt;
    }
#pragma unroll
    for (int k = 0; k < 4; k++) {
        __half2 lo = __floats2half2_rn(acc[0][k], acc[1][k]);
        __half2 hi = __floats2half2_rn(acc[2][k], acc[3][k]);
        uint2 pk = make_uint2(*reinterpret_cast<uint32_t*>(&lo), *reinterpret_cast<uint32_t*>(&hi));
        *reinterpret_cast<uint2*>(&g_Bm[(size_t)(c0 + k) * NN + j0]) = pk;
    }
    if ((tid & 15) == 0) {
        __half2 ulo = __floats2half2_rn(expf(t[0]), expf(t[1]));
        __half2 uhi = __floats2half2_rn(expf(t[2]), expf(t[3]));
        *reinterpret_cast<uint2*>(&g_u[j0]) = make_uint2(*reinterpret_cast<uint32_t*>(&ulo),
                                                         *reinterpret_cast<uint32_t*>(&uhi));
        __half2 vlo = __floats2half2_rn(expf(ALPHA * t[0]), expf(ALPHA * t[1]));
        __half2 vhi = __floats2half2_rn(expf(ALPHA * t[2]), expf(ALPHA * t[3]));
        *reinterpret_cast<uint2*>(&g_v[j0]) = make_uint2(*reinterpret_cast<uint32_t*>(&vlo),
                                                         *reinterpret_cast<uint32_t*>(&vhi));
#pragma unroll
        for (int rr = 0; rr < 4; rr++) {
            g_af[j0 + rr] = expf(s[rr]);
            g_bf[j0 + rr] = expf(ALPHA * s[rr]);
            g_iv[j0 + rr] = expf(-s[rr]);
        }
        __half2 one2 = __floats2half2_rn(1.f, 1.f);
        uint2 ones = make_uint2(*reinterpret_cast<uint32_t*>(&one2), *reinterpret_cast<uint32_t*>(&one2));
        *reinterpret_cast<uint2*>(&g_Bm[(size_t)64 * NN + j0]) = ones;
#pragma unroll
        for (int c = 65; c < NB; c++)
            *reinterpret_cast<uint2*>(&g_Bm[(size_t)c * NN + j0]) = make_uint2(0u, 0u);
    }
}

// ============ Kernel 2: masked GEMM; adj in registers, B-only smem pipeline ============
__device__ __forceinline__ void issue_B(uint32_t sb, int jb, int st, int tid) {
#pragma unroll
    for (int it = 0; it < 5; it++) {
        int v = tid + it * 128;
        if (v < 576) {
            int c = v >> 3, seg = v & 7;
            cp_async16(sb + STAGE0 + st * B_SZ + (uint32_t)(c * 128 + ((seg * 16) ^ ((c & 7) << 4))),
                       g_Bm + (size_t)c * NN + jb + seg * 8);
        }
    }
}

__global__ void __launch_bounds__(128, 2) k_attn(const int* __restrict__ adj) {
    extern __shared__ char smem[];
    const uint32_t sb = smem_u32(smem);
    const int tid = threadIdx.x;
    const int wid = tid >> 5, lane = tid & 31;
    const int r = lane >> 2, cL = lane & 3;
    const int I0 = blockIdx.x * MROWS;
    const int jh = blockIdx.y;
    const int jbase0 = jh * JQ;

    // prologue: B stages 0,1,2
    issue_B(sb, jbase0, 0, tid);
    asm volatile("cp.async.commit_group;" ::: "memory");
    issue_B(sb, jbase0 + KC, 1, tid);
    asm volatile("cp.async.commit_group;" ::: "memory");
    issue_B(sb, jbase0 + 2 * KC, 2, tid);
    asm volatile("cp.async.commit_group;" ::: "memory");

    __half* u_sh = reinterpret_cast<__half*>(smem + U_OFF);
    __half* v_sh = reinterpret_cast<__half*>(smem + V_OFF);
#pragma unroll
    for (int i = tid; i < JQ / 8; i += 128) {
        reinterpret_cast<float4*>(u_sh)[i] = reinterpret_cast<const float4*>(g_u + jbase0)[i];
        reinterpret_cast<float4*>(v_sh)[i] = reinterpret_cast<const float4*>(g_v + jbase0)[i];
    }

    const int ib = I0 + wid * 32 + r;
    __half2 a2[4], b2[4], iv2[4];
#pragma unroll
    for (int p = 0; p < 4; p++) {
        a2[p]  = __float2half2_rn(g_af[ib + p * 8]);
        b2[p]  = __float2half2_rn(g_bf[ib + p * 8]);
        iv2[p] = __float2half2_rn(g_iv[ib + p * 8]);
    }

    const uint32_t swzB = (uint32_t)((lane & 7) << 4);
    const uint32_t kaddB = (uint32_t)(((lane >> 3) & 1) * 16);
    uint32_t rb[5];
#pragma unroll
    for (int g = 0; g < 4; g++)
        rb[g] = (uint32_t)(((2 * g + ((lane >> 4) & 1)) * 8 + (lane & 7)) * 128);
    rb[4] = (uint32_t)((64 + (lane & 7)) * 128);

    // adj register pipeline: per (ksi, rt): w00,w10,w01,w11 -> 32 int2 slots
    const int* aT = adj + (size_t)ib * NN + 2 * cL;   // row ib, col offset 2cL
    int2 wr[4][2][4];
    {
        const int jb = jbase0;
#pragma unroll
        for (int ksi = 0; ksi < 4; ksi++) {
            const int ks = ksi * 16;
#pragma unroll
            for (int rt = 0; rt < 2; rt++) {
                const size_t ro = (size_t)(rt * 16) * NN;
                wr[ksi][rt][0] = *reinterpret_cast<const int2*>(aT + ro + jb + ks);
                wr[ksi][rt][1] = *reinterpret_cast<const int2*>(aT + ro + (size_t)8 * NN + jb + ks);
                wr[ksi][rt][2] = *reinterpret_cast<const int2*>(aT + ro + jb + ks + 8);
                wr[ksi][rt][3] = *reinterpret_cast<const int2*>(aT + ro + (size_t)8 * NN + jb + ks + 8);
            }
        }
    }

    float acc[2][9][4];
#pragma unroll
    for (int rt = 0; rt < 2; rt++)
#pragma unroll
        for (int nt = 0; nt < 9; nt++)
#pragma unroll
            for (int k = 0; k < 4; k++) acc[rt][nt][k] = 0.f;

    for (int q = 0; q < NCHUNK; q++) {
        asm volatile("cp.async.wait_group 2;" ::: "memory");
        __syncthreads();   // single barrier: stage q%4 visible to all; stage (q+3)%4 free

        if (q + 3 < NCHUNK) issue_B(sb, jbase0 + (q + 3) * KC, (q + 3) & 3, tid);
        asm volatile("cp.async.commit_group;" ::: "memory");

        const uint32_t bstB = sb + STAGE0 + (q & 3) * B_SZ;
        const __half* uq = u_sh + q * KC;
        const __half* vq = v_sh + q * KC;
        const int jbn = jbase0 + ((q + 1 < NCHUNK) ? (q + 1) : q) * KC;  // clamp: last reload unused

#pragma unroll
        for (int ksi = 0; ksi < 4; ksi++) {
            const int ks = ksi * 16;
            __half2 u2lo = *reinterpret_cast<const __half2*>(uq + ks + 2 * cL);
            __half2 v2lo = *reinterpret_cast<const __half2*>(vq + ks + 2 * cL);
            __half2 u2hi = *reinterpret_cast<const __half2*>(uq + ks + 8 + 2 * cL);
            __half2 v2hi = *reinterpret_cast<const __half2*>(vq + ks + 8 + 2 * cL);
            const uint32_t inner = ((uint32_t)(ks * 2) + kaddB) ^ swzB;

            uint32_t bb[4][4], b8[2];
#pragma unroll
            for (int g = 0; g < 4; g++)
                ldsm4(bb[g][0], bb[g][1], bb[g][2], bb[g][3], bstB + rb[g] + inner);
            ldsm2(b8[0], b8[1], bstB + rb[4] + inner);

#pragma unroll
            for (int rt = 0; rt < 2; rt++) {
                uint32_t A[4];
                A[0] = frag(wr[ksi][rt][0], u2lo, v2lo, a2[2 * rt], b2[2 * rt], iv2[2 * rt]);
                A[1] = frag(wr[ksi][rt][1], u2lo, v2lo, a2[2 * rt + 1], b2[2 * rt + 1], iv2[2 * rt + 1]);
                A[2] = frag(wr[ksi][rt][2], u2hi, v2hi, a2[2 * rt], b2[2 * rt], iv2[2 * rt]);
                A[3] = frag(wr[ksi][rt][3], u2hi, v2hi, a2[2 * rt + 1], b2[2 * rt + 1], iv2[2 * rt + 1]);

                // refill this (ksi, rt) slot group for chunk q+1
                {
                    const size_t ro = (size_t)(rt * 16) * NN;
                    wr[ksi][rt][0] = *reinterpret_cast<const int2*>(aT + ro + jbn + ks);
                    wr[ksi][rt][1] = *reinterpret_cast<const int2*>(aT + ro + (size_t)8 * NN + jbn + ks);
                    wr[ksi][rt][2] = *reinterpret_cast<const int2*>(aT + ro + jbn + ks + 8);
                    wr[ksi][rt][3] = *reinterpret_cast<const int2*>(aT + ro + (size_t)8 * NN + jbn + ks + 8);
                }

#pragma unroll
                for (int g = 0; g < 4; g++) {
                    mma16816(acc[rt][2 * g], A, bb[g][0], bb[g][1]);
                    mma16816(acc[rt][2 * g + 1], A, bb[g][2], bb[g][3]);
                }
                mma16816(acc[rt][8], A, b8[0], b8[1]);
            }
        }
    }

#pragma unroll
    for (int rt = 0; rt < 2; rt++) {
        const int i0 = ib + rt * 16, i1 = i0 + 8;
        float* p0 = g_part + ((size_t)jh * NN + i0) * NB;
        float* p1 = g_part + ((size_t)jh * NN + i1) * NB;
#pragma unroll
        for (int nt = 0; nt < 9; nt++) {
            const int n = nt * 8 + 2 * cL;
            *reinterpret_cast<float2*>(p0 + n) = make_float2(acc[rt][nt][0], acc[rt][nt][1]);
            *reinterpret_cast<float2*>(p1 + n) = make_float2(acc[rt][nt][2], acc[rt][nt][3]);
        }
    }
}

// ============ Kernel 3: combine quarters, divide (4 elems/thread) ============
__global__ void __launch_bounds__(256) k_combine(float* __restrict__ out) {
    int e = blockIdx.x * 256 + threadIdx.x;
    int i = e >> 4, c = (e & 15) * 4;
    float den = 0.f;
    float4 num = make_float4(0.f, 0.f, 0.f, 0.f);
#pragma unroll
    for (int jh = 0; jh < JSPLIT; jh++) {
        const float* p = g_part + ((size_t)jh * NN + i) * NB;
        float4 x = *reinterpret_cast<const float4*>(p + c);
        num.x += x.x; num.y += x.y; num.z += x.z; num.w += x.w;
        den += p[64];
    }
    float rden = 1.f / den;
    *reinterpret_cast<float4*>(out + (size_t)i * NHID + c) =
        make_float4(num.x * rden, num.y * rden, num.z * rden, num.w * rden);
}

// ============ launcher ============
extern "C" void kernel_launch(void* const* d_in, const int* in_sizes, int n_in,
                              void* d_out, int out_size) {
    const float* inp = (const float*)d_in[0];
    const int* adj   = (const int*)d_in[1];
    const float* W   = (const float*)d_in[2];
    const float* av  = (const float*)d_in[3];
    float* out = (float*)d_out;
    (void)in_sizes; (void)n_in; (void)out_size;

    cudaFuncSetAttribute(k_prep, cudaFuncAttributeMaxDynamicSharedMemorySize, SMEM1_TOTAL);
    cudaFuncSetAttribute(k_attn, cudaFuncAttributeMaxDynamicSharedMemorySize, SMEM3_TOTAL);

    k_prep<<<NN / 64, 256, SMEM1_TOTAL>>>(inp, W, av);
    dim3 g3(NN / MROWS, JSPLIT);
    k_attn<<<g3, 128, SMEM3_TOTAL>>>(adj);
    k_combine<<<(NN * NHID / 4) / 256, 256>>>(out);
}

// round 15
// speedup vs baseline: 1.5957x; 1.1141x over previous
#include <cuda_runtime.h>
#include <cuda_fp16.h>
#include <cstdint>
#include <cstddef>

#define NN 8192
#define EMBD 256
#define NHID 64
#define ALPHA 0.2f

#define MROWS 128
#define KC 64
#define NB 72
#define JSPLIT 4
#define JQ (NN / JSPLIT)          // 2048
#define NCHUNK (JQ / KC)          // 32

// k_attn smem: u/v tables (per j-quarter) then 2 pipeline stages
#define U_OFF 0
#define V_OFF 4096
#define STAGE0 8192
#define ADJ_SZ 32768                       // 128 rows x 256B
#define B_SZ 9216                          // 72 rows x 128B
#define STAGE_SZ (ADJ_SZ + B_SZ)           // 41984
#define NSTAGE 2
#define SMEM3_TOTAL (STAGE0 + NSTAGE * STAGE_SZ)   // 92160

#define SMEM1_TOTAL (EMBD * NHID * 4)      // 64KB W staging

// ---------------- device scratch ----------------
__device__ __half g_Bm[NB * NN];            // [c][j]: h cols (c<64), ones (64), pad 0
__device__ __half g_u[NN], g_v[NN];         // exp(t_j), exp(a*t_j)
__device__ float g_af[NN], g_bf[NN], g_iv[NN];  // exp(s), exp(a*s), exp(-s)
__device__ float g_part[JSPLIT * NN * NB];  // numer 0..63, denom 64

// ---------------- helpers ----------------
__device__ __forceinline__ uint32_t smem_u32(const void* p) {
    uint32_t a;
    asm("{ .reg .u64 t; cvta.to.shared.u64 t, %1; cvt.u32.u64 %0, t; }" : "=r"(a) : "l"(p));
    return a;
}
__device__ __forceinline__ void cp_async16(uint32_t dst, const void* src) {
    asm volatile("cp.async.cg.shared.global [%0], [%1], 16;" :: "r"(dst), "l"(src));
}
__device__ __forceinline__ void ldsm4(uint32_t& r0, uint32_t& r1, uint32_t& r2, uint32_t& r3, uint32_t a) {
    asm volatile("ldmatrix.sync.aligned.m8n8.x4.shared.b16 {%0,%1,%2,%3}, [%4];"
                 : "=r"(r0), "=r"(r1), "=r"(r2), "=r"(r3) : "r"(a));
}
__device__ __forceinline__ void ldsm2(uint32_t& r0, uint32_t& r1, uint32_t a) {
    asm volatile("ldmatrix.sync.aligned.m8n8.x2.shared.b16 {%0,%1}, [%2];"
                 : "=r"(r0), "=r"(r1) : "r"(a));
}
__device__ __forceinline__ void mma16816(float* d, const uint32_t* a, uint32_t b0, uint32_t b1) {
    asm volatile("mma.sync.aligned.m16n8k16.row.col.f32.f16.f16.f32 "
                 "{%0,%1,%2,%3}, {%4,%5,%6,%7}, {%8,%9}, {%0,%1,%2,%3};"
                 : "+f"(d[0]), "+f"(d[1]), "+f"(d[2]), "+f"(d[3])
                 : "r"(a[0]), "r"(a[1]), "r"(a[2]), "r"(a[3]), "r"(b0), "r"(b1));
}
// P pair for 2 j's: adj * (u>=inva ? a*u : b*v), packed f16x2
__device__ __forceinline__ uint32_t frag(int2 w, __half2 u2, __half2 v2,
                                         __half2 a2, __half2 b2, __half2 iv2) {
    __half2 sel = __hge2(u2, iv2);
    __half2 au = __hmul2(a2, u2);
    __half2 bv = __hmul2(b2, v2);
    __half2 val = __hfma2(sel, __hsub2(au, bv), bv);
    uint32_t m = (uint32_t)w.x * 0x3C00u + (uint32_t)w.y * 0x3C000000u;
    __half2 res = __hmul2(val, *reinterpret_cast<__half2*>(&m));
    return *reinterpret_cast<uint32_t*>(&res);
}

// ===== Kernel 1: h = input@W + prep, 4 rows x 4 cols per thread =====
__global__ void __launch_bounds__(256) k_prep(const float* __restrict__ inp,
                                              const float* __restrict__ W,
                                              const float* __restrict__ av) {
    extern __shared__ float Ws[];   // 64KB
    const int tid = threadIdx.x;
#pragma unroll
    for (int i = tid; i < (EMBD * NHID) / 4; i += 256)
        reinterpret_cast<float4*>(Ws)[i] = __ldg(reinterpret_cast<const float4*>(W) + i);
    __syncthreads();

    const int rg = tid >> 4;                    // 16 row groups
    const int j0 = blockIdx.x * 64 + rg * 4;    // 4 rows/thread
    const int c0 = (tid & 15) * 4;              // 4 cols/thread
    float acc[4][4];
#pragma unroll
    for (int rr = 0; rr < 4; rr++)
#pragma unroll
        for (int k = 0; k < 4; k++) acc[rr][k] = 0.f;

    const float* ir = inp + (size_t)j0 * EMBD;
#pragma unroll
    for (int k0 = 0; k0 < EMBD; k0 += 8) {
        float4 xs[4][2];
#pragma unroll
        for (int rr = 0; rr < 4; rr++) {
            xs[rr][0] = __ldg(reinterpret_cast<const float4*>(ir + (size_t)rr * EMBD + k0));
            xs[rr][1] = __ldg(reinterpret_cast<const float4*>(ir + (size_t)rr * EMBD + k0 + 4));
        }
#pragma unroll
        for (int kb = 0; kb < 8; kb++) {
            float4 w = *reinterpret_cast<const float4*>(Ws + (k0 + kb) * NHID + c0);
#pragma unroll
            for (int rr = 0; rr < 4; rr++) {
                float xv = (&xs[rr][kb >> 2].x)[kb & 3];
                acc[rr][0] += xv * w.x; acc[rr][1] += xv * w.y;
                acc[rr][2] += xv * w.z; acc[rr][3] += xv * w.w;
            }
        }
    }
    // s,t per row via 16-lane reductions
    float s[4], t[4];
#pragma unroll
    for (int rr = 0; rr < 4; rr++) {
        float ss = 0.f, tt = 0.f;
#pragma unroll
        for (int k = 0; k < 4; k++) {
            ss += acc[rr][k] * __ldg(av + c0 + k);
            tt += acc[rr][k] * __ldg(av + 64 + c0 + k);
        }
#pragma unroll
        for (int o = 1; o < 16; o <<= 1) {
            ss += __shfl_xor_sync(0xFFFFFFFFu, ss, o);
            tt += __shfl_xor_sync(0xFFFFFFFFu, tt, o);
        }
        s[rr] = ss; t[rr] = tt;
    }
    // B matrix: 4x4 block transposed -> 8B stores (4 adjacent j per col)
#pragma unroll
    for (int k = 0; k < 4; k++) {
        __half2 lo = __floats2half2_rn(acc[0][k], acc[1][k]);
        __half2 hi = __floats2half2_rn(acc[2][k], acc[3][k]);
        uint2 pk = make_uint2(*reinterpret_cast<uint32_t*>(&lo), *reinterpret_cast<uint32_t*>(&hi));
        *reinterpret_cast<uint2*>(&g_Bm[(size_t)(c0 + k) * NN + j0]) = pk;
    }
    if ((tid & 15) == 0) {
        __half2 ulo = __floats2half2_rn(expf(t[0]), expf(t[1]));
        __half2 uhi = __floats2half2_rn(expf(t[2]), expf(t[3]));
        *reinterpret_cast<uint2*>(&g_u[j0]) = make_uint2(*reinterpret_cast<uint32_t*>(&ulo),
                                                         *reinterpret_cast<uint32_t*>(&uhi));
        __half2 vlo = __floats2half2_rn(expf(ALPHA * t[0]), expf(ALPHA * t[1]));
        __half2 vhi = __floats2half2_rn(expf(ALPHA * t[2]), expf(ALPHA * t[3]));
        *reinterpret_cast<uint2*>(&g_v[j0]) = make_uint2(*reinterpret_cast<uint32_t*>(&vlo),
                                                         *reinterpret_cast<uint32_t*>(&vhi));
#pragma unroll
        for (int rr = 0; rr < 4; rr++) {
            g_af[j0 + rr] = expf(s[rr]);
            g_bf[j0 + rr] = expf(ALPHA * s[rr]);
            g_iv[j0 + rr] = expf(-s[rr]);
        }
        __half2 one2 = __floats2half2_rn(1.f, 1.f);
        uint2 ones = make_uint2(*reinterpret_cast<uint32_t*>(&one2), *reinterpret_cast<uint32_t*>(&one2));
        *reinterpret_cast<uint2*>(&g_Bm[(size_t)64 * NN + j0]) = ones;
#pragma unroll
        for (int c = 65; c < NB; c++)
            *reinterpret_cast<uint2*>(&g_Bm[(size_t)c * NN + j0]) = make_uint2(0u, 0u);
    }
}

// ============ Kernel 2: masked GEMM, 4 warps x 32 rows, 2 CTAs/SM ============
__device__ __forceinline__ void issue_chunk(uint32_t sb, const int* __restrict__ adj,
                                            int I0, int jb, int st, int tid) {
    const uint32_t stage = sb + STAGE0 + st * STAGE_SZ;
#pragma unroll
    for (int it = 0; it < 16; it++) {
        int u = tid + it * 128;
        int row = u >> 4, ku = u & 15;
        cp_async16(stage + (uint32_t)(row * 256 + ((ku * 16) ^ ((row & 7) << 4))),
                   adj + (size_t)(I0 + row) * NN + jb + ku * 4);
    }
    const uint32_t bst = stage + ADJ_SZ;
#pragma unroll
    for (int it = 0; it < 5; it++) {
        int v = tid + it * 128;
        if (v < 576) {
            int c = v >> 3, seg = v & 7;
            cp_async16(bst + (uint32_t)(c * 128 + ((seg * 16) ^ ((c & 7) << 4))),
                       g_Bm + (size_t)c * NN + jb + seg * 8);
        }
    }
    asm volatile("cp.async.commit_group;" ::: "memory");
}

__global__ void __launch_bounds__(128, 2) k_attn(const int* __restrict__ adj) {
    extern __shared__ char smem[];
    const uint32_t sb = smem_u32(smem);
    const int tid = threadIdx.x;
    const int wid = tid >> 5, lane = tid & 31;
    const int r = lane >> 2, cL = lane & 3;
    const int I0 = blockIdx.x * MROWS;
    const int jh = blockIdx.y;
    const int jbase0 = jh * JQ;

    issue_chunk(sb, adj, I0, jbase0, 0, tid);
    issue_chunk(sb, adj, I0, jbase0 + KC, 1, tid);

    __half* u_sh = reinterpret_cast<__half*>(smem + U_OFF);
    __half* v_sh = reinterpret_cast<__half*>(smem + V_OFF);
#pragma unroll
    for (int i = tid; i < JQ / 8; i += 128) {
        reinterpret_cast<float4*>(u_sh)[i] = reinterpret_cast<const float4*>(g_u + jbase0)[i];
        reinterpret_cast<float4*>(v_sh)[i] = reinterpret_cast<const float4*>(g_v + jbase0)[i];
    }

    const int ib = I0 + wid * 32 + r;
    __half2 a2[4], b2[4], iv2[4];
#pragma unroll
    for (int p = 0; p < 4; p++) {
        a2[p]  = __float2half2_rn(g_af[ib + p * 8]);
        b2[p]  = __float2half2_rn(g_bf[ib + p * 8]);
        iv2[p] = __float2half2_rn(g_iv[ib + p * 8]);
    }

    const uint32_t swzA = (uint32_t)(r << 4);
    const uint32_t swzB = (uint32_t)((lane & 7) << 4);
    const uint32_t kaddB = (uint32_t)(((lane >> 3) & 1) * 16);
    uint32_t rb[5];
#pragma unroll
    for (int g = 0; g < 4; g++)
        rb[g] = (uint32_t)(((2 * g + ((lane >> 4) & 1)) * 8 + (lane & 7)) * 128);
    rb[4] = (uint32_t)((64 + (lane & 7)) * 128);

    float acc[2][9][4];
#pragma unroll
    for (int rt = 0; rt < 2; rt++)
#pragma unroll
        for (int nt = 0; nt < 9; nt++)
#pragma unroll
            for (int k = 0; k < 4; k++) acc[rt][nt][k] = 0.f;

    for (int q = 0; q < NCHUNK; q++) {
        if (q < NCHUNK - 1) asm volatile("cp.async.wait_group 1;" ::: "memory");
        else                asm volatile("cp.async.wait_group 0;" ::: "memory");
        __syncthreads();

        const char* adjp = smem + STAGE0 + (q & 1) * STAGE_SZ;
        const uint32_t bstB = sb + STAGE0 + (q & 1) * STAGE_SZ + ADJ_SZ;
        const __half* uq = u_sh + q * KC;
        const __half* vq = v_sh + q * KC;
        const int rbase = wid * 32 + r;

#pragma unroll
        for (int ksi = 0; ksi < 4; ksi++) {
            const int ks = ksi * 16;
            __half2 u2lo = *reinterpret_cast<const __half2*>(uq + ks + 2 * cL);
            __half2 v2lo = *reinterpret_cast<const __half2*>(vq + ks + 2 * cL);
            __half2 u2hi = *reinterpret_cast<const __half2*>(uq + ks + 8 + 2 * cL);
            __half2 v2hi = *reinterpret_cast<const __half2*>(vq + ks + 8 + 2 * cL);
            const uint32_t ka = (uint32_t)(ks * 4 + cL * 8);
            const uint32_t inner = ((uint32_t)(ks * 2) + kaddB) ^ swzB;

            uint32_t bb[4][4], b8[2];
#pragma unroll
            for (int g = 0; g < 4; g++)
                ldsm4(bb[g][0], bb[g][1], bb[g][2], bb[g][3], bstB + rb[g] + inner);
            ldsm2(b8[0], b8[1], bstB + rb[4] + inner);

#pragma unroll
            for (int rt = 0; rt < 2; rt++) {
                const int r0 = rbase + rt * 16;
                int2 w00 = *reinterpret_cast<const int2*>(adjp + r0 * 256 + (ka ^ swzA));
                int2 w10 = *reinterpret_cast<const int2*>(adjp + (r0 + 8) * 256 + (ka ^ swzA));
                int2 w01 = *reinterpret_cast<const int2*>(adjp + r0 * 256 + ((ka + 32) ^ swzA));
                int2 w11 = *reinterpret_cast<const int2*>(adjp + (r0 + 8) * 256 + ((ka + 32) ^ swzA));

                uint32_t A[4];
                A[0] = frag(w00, u2lo, v2lo, a2[2 * rt], b2[2 * rt], iv2[2 * rt]);
                A[1] = frag(w10, u2lo, v2lo, a2[2 * rt + 1], b2[2 * rt + 1], iv2[2 * rt + 1]);
                A[2] = frag(w01, u2hi, v2hi, a2[2 * rt], b2[2 * rt], iv2[2 * rt]);
                A[3] = frag(w11, u2hi, v2hi, a2[2 * rt + 1], b2[2 * rt + 1], iv2[2 * rt + 1]);

#pragma unroll
                for (int g = 0; g < 4; g++) {
                    mma16816(acc[rt][2 * g], A, bb[g][0], bb[g][1]);
                    mma16816(acc[rt][2 * g + 1], A, bb[g][2], bb[g][3]);
                }
                mma16816(acc[rt][8], A, b8[0], b8[1]);
            }
        }
        __syncthreads();
        if (q + 2 < NCHUNK)
            issue_chunk(sb, adj, I0, jbase0 + (q + 2) * KC, q & 1, tid);
    }

#pragma unroll
    for (int rt = 0; rt < 2; rt++) {
        const int i0 = ib + rt * 16, i1 = i0 + 8;
        float* p0 = g_part + ((size_t)jh * NN + i0) * NB;
        float* p1 = g_part + ((size_t)jh * NN + i1) * NB;
#pragma unroll
        for (int nt = 0; nt < 9; nt++) {
            const int n = nt * 8 + 2 * cL;
            *reinterpret_cast<float2*>(p0 + n) = make_float2(acc[rt][nt][0], acc[rt][nt][1]);
            *reinterpret_cast<float2*>(p1 + n) = make_float2(acc[rt][nt][2], acc[rt][nt][3]);
        }
    }
}

// ============ Kernel 3: combine quarters, divide (2 elems/thread) ============
__global__ void __launch_bounds__(256) k_combine(float* __restrict__ out) {
    int e = blockIdx.x * 256 + threadIdx.x;     // pair index
    int i = e >> 5, c = (e & 31) * 2;
    float den = 0.f;
    float2 num = make_float2(0.f, 0.f);
#pragma unroll
    for (int jh = 0; jh < JSPLIT; jh++) {
        const float* p = g_part + ((size_t)jh * NN + i) * NB;
        float2 x = *reinterpret_cast<const float2*>(p + c);
        num.x += x.x; num.y += x.y;
        den += p[64];
    }
    float rden = 1.f / den;
    *reinterpret_cast<float2*>(out + (size_t)i * NHID + c) =
        make_float2(num.x * rden, num.y * rden);
}

// ============ launcher ============
extern "C" void kernel_launch(void* const* d_in, const int* in_sizes, int n_in,
                              void* d_out, int out_size) {
    const float* inp = (const float*)d_in[0];
    const int* adj   = (const int*)d_in[1];
    const float* W   = (const float*)d_in[2];
    const float* av  = (const float*)d_in[3];
    float* out = (float*)d_out;
    (void)in_sizes; (void)n_in; (void)out_size;

    cudaFuncSetAttribute(k_prep, cudaFuncAttributeMaxDynamicSharedMemorySize, SMEM1_TOTAL);
    cudaFuncSetAttribute(k_attn, cudaFuncAttributeMaxDynamicSharedMemorySize, SMEM3_TOTAL);

    k_prep<<<NN / 64, 256, SMEM1_TOTAL>>>(inp, W, av);
    dim3 g3(NN / MROWS, JSPLIT);
    k_attn<<<g3, 128, SMEM3_TOTAL>>>(adj);
    k_combine<<<(NN * NHID / 2) / 256, 256>>>(out);
}